// round 1
// baseline (speedup 1.0000x reference)
#include <cuda_runtime.h>
#include <math.h>

// ---------------- problem constants ----------------
#define NB    4      // batch
#define NLVL  3
#define NA    9      // anchors per cell
#define NC    80     // NUM_FG
#define PRE   1000
#define TOPN  100
#define NCAP  8192   // candidate buffer per (img,lvl)
#define LOG_MAX_F 4.135166556742356f
#define IMG_OFF 641.0f   // IMG + 1

// ---------------- device scratch (static, allowed) ----------------
__device__ unsigned int       g_hist[NB][NLVL][4096];
__device__ unsigned long long g_cand[NB][NLVL][NCAP];
__device__ unsigned int       g_cnt [NB][NLVL];
__device__ unsigned int       g_thr [NB][NLVL];
__device__ float              g_rois[NB][3000][6];   // x1,y1,x2,y2,score,cls

// ---------------- helpers ----------------
__device__ __forceinline__ void bitonic_desc(unsigned long long* s, int n, int tid, int nt) {
    for (int k = 2; k <= n; k <<= 1) {
        for (int j = k >> 1; j > 0; j >>= 1) {
            for (int i = tid; i < n; i += nt) {
                int ixj = i ^ j;
                if (ixj > i) {
                    unsigned long long a = s[i], b = s[ixj];
                    bool sw = ((i & k) == 0) ? (a < b) : (a > b); // descending
                    if (sw) { s[i] = b; s[ixj] = a; }
                }
            }
            __syncthreads();
        }
    }
}

// ---------------- kernels ----------------
__global__ void zero_kernel() {
    int i = blockIdx.x * blockDim.x + threadIdx.x;
    if (i < NB * NLVL * 4096) ((unsigned int*)g_hist)[i] = 0;
    if (i < NB * NLVL) {
        ((unsigned int*)g_cnt)[i] = 0;
        ((unsigned int*)g_thr)[i] = 0;
    }
}

// histogram of positive-tail logits (>= 1.0f), bins = ordered-float-key >> 20
__global__ void hist_kernel(const float* __restrict__ cls, int lvl, int nvec) {
    __shared__ unsigned int sh[4096];
    for (int i = threadIdx.x; i < 4096; i += blockDim.x) sh[i] = 0;
    __syncthreads();
    int b = blockIdx.y;
    const float4* p = (const float4*)(cls + (size_t)b * (size_t)nvec * 4);
    for (int i = blockIdx.x * blockDim.x + threadIdx.x; i < nvec; i += gridDim.x * blockDim.x) {
        float4 v = p[i];
        float c[4] = {v.x, v.y, v.z, v.w};
#pragma unroll
        for (int q = 0; q < 4; q++) {
            if (c[q] >= 1.0f) {
                unsigned int key = __float_as_uint(c[q]) | 0x80000000u;
                atomicAdd(&sh[key >> 20], 1u);
            }
        }
    }
    __syncthreads();
    for (int i = threadIdx.x; i < 4096; i += blockDim.x)
        if (sh[i]) atomicAdd(&g_hist[b][lvl][i], sh[i]);
}

// find largest bin T with suffix_count(T) >= PRE; store key threshold T<<20
__global__ void thresh_kernel() {
    int b = blockIdx.x / NLVL, l = blockIdx.x % NLVL;
    __shared__ unsigned int h[4096];
    __shared__ unsigned int segsum[256];
    int t = threadIdx.x;  // 256 threads
    unsigned int mysum = 0;
#pragma unroll
    for (int q = 0; q < 16; q++) {
        unsigned int v = g_hist[b][l][t * 16 + q];
        h[t * 16 + q] = v;
        mysum += v;
    }
    segsum[t] = mysum;
    __syncthreads();
    // inclusive suffix scan over 256 segments
    for (int d = 1; d < 256; d <<= 1) {
        unsigned int v = segsum[t];
        if (t + d < 256) v += segsum[t + d];
        __syncthreads();
        segsum[t] = v;
        __syncthreads();
    }
    unsigned int cum = (t < 255) ? segsum[t + 1] : 0u;  // suffix above my segment
    for (int q = 15; q >= 0; q--) {
        int bin = t * 16 + q;
        unsigned int hv = h[bin];
        cum += hv;
        if (cum >= PRE && (cum - hv) < PRE) {
            g_thr[b][l] = ((unsigned int)bin) << 20;
        }
    }
}

// gather candidates with key >= threshold; score = fp32 1/(1+expf(-x)) (XLA logistic)
__global__ void gather_kernel(const float* __restrict__ cls, int lvl, int nvec, int HW) {
    int b = blockIdx.y;
    unsigned int thr = g_thr[b][lvl];
    const float4* p = (const float4*)(cls + (size_t)b * (size_t)nvec * 4);
    for (int i = blockIdx.x * blockDim.x + threadIdx.x; i < nvec; i += gridDim.x * blockDim.x) {
        float4 v = p[i];
        float c[4] = {v.x, v.y, v.z, v.w};
#pragma unroll
        for (int q = 0; q < 4; q++) {
            float x = c[q];
            if (x >= 1.0f) {
                unsigned int key = __float_as_uint(x) | 0x80000000u;
                if (key >= thr) {
                    int m = i * 4 + q;            // index in (720, H, W) layout
                    int ch = m / HW;
                    int pp = m - ch * HW;         // h*W + w
                    int a = ch / NC;
                    int cc = ch - a * NC;
                    unsigned int f = (unsigned int)((pp * NA + a) * NC + cc);
                    float score = 1.0f / (1.0f + expf(-x));
                    unsigned long long k64 =
                        ((unsigned long long)__float_as_uint(score) << 32) |
                        (unsigned long long)(0xFFFFFFFFu - f);
                    unsigned int pos = atomicAdd(&g_cnt[b][lvl], 1u);
                    if (pos < NCAP) g_cand[b][lvl][pos] = k64;
                }
            }
        }
    }
}

// per (img,lvl): sort candidates desc, take top-1000, decode boxes into g_rois
__global__ void topk_decode_kernel(const float* __restrict__ loc,
                                   const float* __restrict__ info,
                                   int lvl, int H, int W, int stride) {
    extern __shared__ unsigned long long sk[];  // 8192 keys
    int b = blockIdx.x, tid = threadIdx.x, nt = blockDim.x;
    unsigned int cnt = g_cnt[b][lvl];
    if (cnt > NCAP) cnt = NCAP;
    for (int i = tid; i < NCAP; i += nt)
        sk[i] = (i < (int)cnt) ? g_cand[b][lvl][i] : 0ull;
    __syncthreads();
    bitonic_desc(sk, NCAP, tid, nt);

    int HW = H * W;
    float imh = info[b * 5 + 0];
    float imw = info[b * 5 + 1];

    for (int r = tid; r < PRE; r += nt) {
        unsigned long long key = sk[r];
        float* row = g_rois[b][lvl * PRE + r];
        if (key == 0ull) {
            row[0] = row[1] = row[2] = row[3] = row[4] = row[5] = 0.0f;
            continue;
        }
        unsigned int f = 0xFFFFFFFFu - (unsigned int)(key & 0xFFFFFFFFu);
        float score = __uint_as_float((unsigned int)(key >> 32));
        int aidx = f / NC;
        int cc = f - aidx * NC;
        int pp = aidx / NA;
        int a = aidx - pp * NA;
        int hh = pp / W;
        int ww = pp - hh * W;

        // base anchor in double (matches numpy float64 then .astype(float32))
        int ri = a / 3, si = a % 3;
        double ratio = (ri == 0) ? 0.5 : ((ri == 1) ? 1.0 : 2.0);
        double scale = (si == 0) ? 4.0 : ((si == 1) ? 8.0 : 16.0);
        double basew = (double)stride;
        double ctr = (basew - 1.0) * 0.5;
        double wsd = rint(sqrt(basew * basew / ratio));
        double hsd = rint(wsd * ratio);
        double ax1 = ctr - 0.5 * (wsd - 1.0), ay1 = ctr - 0.5 * (hsd - 1.0);
        double ax2 = ctr + 0.5 * (wsd - 1.0), ay2 = ctr + 0.5 * (hsd - 1.0);
        double aw = ax2 - ax1 + 1.0, ah = ay2 - ay1 + 1.0;
        double cxd = ax1 + 0.5 * (aw - 1.0), cyd = ay1 + 0.5 * (ah - 1.0);
        double swd = aw * scale, shd = ah * scale;
        float bx1 = (float)(cxd - 0.5 * (swd - 1.0));
        float by1 = (float)(cyd - 0.5 * (shd - 1.0));
        float bx2 = (float)(cxd + 0.5 * (swd - 1.0));
        float by2 = (float)(cyd + 0.5 * (shd - 1.0));
        float shx = (float)(ww * stride), shy = (float)(hh * stride);
        float Ax1 = shx + bx1, Ay1 = shy + by1, Ax2 = shx + bx2, Ay2 = shy + by2;

        // deltas: loc[(b*36 + a*4 + j)*HW + pp]
        size_t lbase = ((size_t)b * (NA * 4) + (size_t)a * 4) * (size_t)HW + (size_t)pp;
        float dx = loc[lbase];
        float dy = loc[lbase + HW];
        float dw = loc[lbase + 2 * (size_t)HW];
        float dh = loc[lbase + 3 * (size_t)HW];

        float ws = Ax2 - Ax1 + 1.0f, hs = Ay2 - Ay1 + 1.0f;
        float cx = Ax1 + 0.5f * (ws - 1.0f), cy = Ay1 + 0.5f * (hs - 1.0f);
        dw = fminf(fmaxf(dw, -LOG_MAX_F), LOG_MAX_F);
        dh = fminf(fmaxf(dh, -LOG_MAX_F), LOG_MAX_F);
        float pcx = dx * ws + cx, pcy = dy * hs + cy;
        float pw = expf(dw) * ws, ph = expf(dh) * hs;
        float x1 = pcx - 0.5f * (pw - 1.0f);
        float y1 = pcy - 0.5f * (ph - 1.0f);
        float x2 = pcx + 0.5f * (pw - 1.0f);
        float y2 = pcy + 0.5f * (ph - 1.0f);
        x1 = fminf(fmaxf(x1, 0.0f), imw - 1.0f);
        y1 = fminf(fmaxf(y1, 0.0f), imh - 1.0f);
        x2 = fminf(fmaxf(x2, 0.0f), imw - 1.0f);
        y2 = fminf(fmaxf(y2, 0.0f), imh - 1.0f);

        row[0] = x1; row[1] = y1; row[2] = x2; row[3] = y2;
        row[4] = score;
        row[5] = (float)(cc + 1);
    }
}

// per image: sort 3000 rois by (score desc, pos asc), greedy NMS (early exit at 100), emit
__global__ void nms_kernel(float* __restrict__ out) {
    extern __shared__ char smem[];
    unsigned long long* keys = (unsigned long long*)smem;        // 4096 * 8
    float* ox1  = (float*)(keys + 4096);                          // 3072 each
    float* oy1  = ox1 + 3072;
    float* ox2  = oy1 + 3072;
    float* oy2  = ox2 + 3072;
    float* area = oy2 + 3072;
    int*   spos = (int*)(area + 3072);                            // 3072
    unsigned char* supp = (unsigned char*)(spos + 3072);          // 3072
    __shared__ int s_i, s_k, s_cur;
    __shared__ int s_kept[TOPN];

    int b = blockIdx.x, tid = threadIdx.x, nt = blockDim.x;

    for (int i = tid; i < 4096; i += nt) {
        unsigned long long k = 0ull;
        if (i < 3000) {
            float sc = g_rois[b][i][4];
            k = ((unsigned long long)__float_as_uint(sc) << 32) |
                (unsigned long long)(0xFFFFFFFFu - (unsigned int)i);
        }
        keys[i] = k;
    }
    __syncthreads();
    bitonic_desc(keys, 4096, tid, nt);

    for (int i = tid; i < 3000; i += nt) {
        int pos = (int)(0xFFFFFFFFu - (unsigned int)(keys[i] & 0xFFFFFFFFu));
        spos[i] = pos;
        const float* rw = g_rois[b][pos];
        float off = rw[5] * IMG_OFF;
        float a1 = rw[0] + off, b1 = rw[1] + off;
        float a2 = rw[2] + off, b2 = rw[3] + off;
        ox1[i] = a1; oy1[i] = b1; ox2[i] = a2; oy2[i] = b2;
        area[i] = (a2 - a1 + 1.0f) * (b2 - b1 + 1.0f);
        supp[i] = 0;
    }
    if (tid == 0) { s_i = 0; s_k = 0; }
    __syncthreads();

    for (;;) {
        if (tid == 0) {
            int i = s_i;
            while (i < 3000 && supp[i]) i++;
            if (i < 3000 && s_k < TOPN) {
                s_kept[s_k] = i; s_k++; s_i = i + 1; s_cur = i;
            } else {
                s_cur = -1;
            }
        }
        __syncthreads();
        int i = s_cur;
        if (i < 0) break;
        if (s_k >= TOPN) break;   // 100th kept recorded; its suppression is irrelevant
        float X1 = ox1[i], Y1 = oy1[i], X2 = ox2[i], Y2 = oy2[i], AR = area[i];
        for (int j = i + 1 + tid; j < 3000; j += nt) {
            if (supp[j]) continue;
            float ltx = fmaxf(X1, ox1[j]);
            float lty = fmaxf(Y1, oy1[j]);
            float rbx = fminf(X2, ox2[j]);
            float rby = fminf(Y2, oy2[j]);
            float w = fmaxf((rbx - ltx) + 1.0f, 0.0f);
            float h = fmaxf((rby - lty) + 1.0f, 0.0f);
            float inter = w * h;
            float iou = inter / ((AR + area[j]) - inter);
            if (iou > 0.5f) supp[j] = 1;
        }
        __syncthreads();
    }
    __syncthreads();

    for (int r = tid; r < TOPN; r += nt) {
        float* o = out + ((size_t)b * TOPN + r) * 7;
        if (r < s_k) {
            int pos = spos[s_kept[r]];
            const float* rw = g_rois[b][pos];
            o[0] = (float)b;
            o[1] = rw[0]; o[2] = rw[1]; o[3] = rw[2]; o[4] = rw[3];
            o[5] = rw[4]; o[6] = rw[5];
        } else {
            o[0] = o[1] = o[2] = o[3] = o[4] = o[5] = o[6] = 0.0f;
        }
    }
}

// ---------------- host launcher ----------------
extern "C" void kernel_launch(void* const* d_in, const int* in_sizes, int n_in,
                              void* d_out, int out_size) {
    (void)in_sizes; (void)n_in; (void)out_size;
    const float* cls0 = (const float*)d_in[0];
    const float* loc0 = (const float*)d_in[1];
    const float* cls1 = (const float*)d_in[2];
    const float* loc1 = (const float*)d_in[3];
    const float* cls2 = (const float*)d_in[4];
    const float* loc2 = (const float*)d_in[5];
    const float* info = (const float*)d_in[6];
    float* out = (float*)d_out;

    cudaFuncSetAttribute(topk_decode_kernel,
                         cudaFuncAttributeMaxDynamicSharedMemorySize, 65536);
    cudaFuncSetAttribute(nms_kernel,
                         cudaFuncAttributeMaxDynamicSharedMemorySize, 112640);

    zero_kernel<<<192, 256>>>();

    // nvec = per-image float4 count = 720*H*W/4
    hist_kernel<<<dim3(256, NB), 256>>>(cls0, 0, 1152000);
    hist_kernel<<<dim3(64,  NB), 256>>>(cls1, 1, 288000);
    hist_kernel<<<dim3(16,  NB), 256>>>(cls2, 2, 72000);

    thresh_kernel<<<NB * NLVL, 256>>>();

    gather_kernel<<<dim3(256, NB), 256>>>(cls0, 0, 1152000, 6400);
    gather_kernel<<<dim3(64,  NB), 256>>>(cls1, 1, 288000, 1600);
    gather_kernel<<<dim3(16,  NB), 256>>>(cls2, 2, 72000, 400);

    topk_decode_kernel<<<NB, 1024, 65536>>>(loc0, info, 0, 80, 80, 8);
    topk_decode_kernel<<<NB, 1024, 65536>>>(loc1, info, 1, 40, 40, 16);
    topk_decode_kernel<<<NB, 1024, 65536>>>(loc2, info, 2, 20, 20, 32);

    nms_kernel<<<NB, 1024, 112640>>>(out);
}

// round 2
// speedup vs baseline: 2.3600x; 2.3600x over previous
#include <cuda_runtime.h>
#include <math.h>

// ---------------- problem constants ----------------
#define NB    4
#define NLVL  3
#define NA    9
#define NC    80
#define PRE   1000
#define TOPN  100
#define NCAP  8192
#define NCH   47          // ceil(3000/64)
#define LOG_MAX_F 4.135166556742356f
#define IMG_OFF 641.0f

typedef unsigned long long u64;

// ---------------- device scratch ----------------
__device__ unsigned int g_hist[12][4096];
__device__ unsigned int g_cnt [12];
__device__ unsigned int g_thr [12];
__device__ unsigned int g_need[12];
__device__ u64          g_cand[12][NCAP];
__device__ float        g_rois[NB][3000][6];
__device__ int          g_spos[NB][3008];
__device__ float        g_sx1[NB][3008], g_sy1[NB][3008], g_sx2[NB][3008], g_sy2[NB][3008], g_sar[NB][3008];
__device__ u64          g_mask[NB][3000 * NCH];

// ---------------- helpers ----------------
__device__ __forceinline__ void bitonic_desc(u64* s, int n, int tid, int nt) {
    for (int k = 2; k <= n; k <<= 1) {
        for (int j = k >> 1; j > 0; j >>= 1) {
            for (int i = tid; i < n; i += nt) {
                int ixj = i ^ j;
                if (ixj > i) {
                    u64 a = s[i], b = s[ixj];
                    bool sw = ((i & k) == 0) ? (a < b) : (a > b);
                    if (sw) { s[i] = b; s[ixj] = a; }
                }
            }
            __syncthreads();
        }
    }
}

struct LvlMap {
    int lvl, b, start, len, HW;
    const float4* p;
};
__device__ __forceinline__ LvlMap map_block(int bx, const float4* c0, const float4* c1, const float4* c2) {
    LvlMap m;
    int li, per, nvec;
    if (bx < 1152)      { m.lvl = 0; li = bx;        per = 288; nvec = 1152000; m.HW = 6400; m.p = c0; }
    else if (bx < 1440) { m.lvl = 1; li = bx - 1152; per = 72;  nvec = 288000;  m.HW = 1600; m.p = c1; }
    else                { m.lvl = 2; li = bx - 1440; per = 24;  nvec = 72000;   m.HW = 400;  m.p = c2; }
    m.b = li / per;
    int chunk = li - m.b * per;
    m.len = nvec / per;
    m.start = chunk * m.len;
    m.p += (size_t)m.b * nvec;
    return m;
}

__device__ __forceinline__ void push_cand(int id, int m, int HW, float x) {
    int ch = m / HW;
    int pp = m - ch * HW;
    int a  = ch / NC;
    int cc = ch - a * NC;
    unsigned int f = (unsigned int)((pp * NA + a) * NC + cc);
    float score = 1.0f / (1.0f + expf(-x));
    u64 k64 = ((u64)__float_as_uint(score) << 32) | (u64)(0xFFFFFFFFu - f);
    unsigned int pos = atomicAdd(&g_cnt[id], 1u);
    if (pos < NCAP) g_cand[id][pos] = k64;
}

// ---------------- kernels ----------------
__global__ void zero_kernel() {
    int i = blockIdx.x * blockDim.x + threadIdx.x;
    if (i < 12 * 4096) ((unsigned int*)g_hist)[i] = 0;
    if (i < 12) g_cnt[i] = 0;
}

// one streaming pass: histogram (fallback support) + speculative gather
__global__ void __launch_bounds__(256) passA_kernel(const float4* __restrict__ c0,
                                                    const float4* __restrict__ c1,
                                                    const float4* __restrict__ c2) {
    __shared__ unsigned int sh[4096];
    LvlMap m = map_block(blockIdx.x, c0, c1, c2);
    int id = m.b * 3 + m.lvl;
    float specT = (m.lvl == 0) ? 3.2f : ((m.lvl == 1) ? 2.8f : 2.3f);
    unsigned int specKey = __float_as_uint(specT) | 0x80000000u;

    for (int i = threadIdx.x; i < 4096; i += 256) sh[i] = 0;
    __syncthreads();

    int e = m.start + m.len;
    for (int i = m.start + threadIdx.x; i < e; i += 256) {
        float4 v = m.p[i];
        float c[4] = {v.x, v.y, v.z, v.w};
#pragma unroll
        for (int q = 0; q < 4; q++) {
            float x = c[q];
            if (x >= 1.0f) {
                unsigned int key = __float_as_uint(x) | 0x80000000u;
                atomicAdd(&sh[key >> 20], 1u);
                if (key >= specKey) push_cand(id, i * 4 + q, m.HW, x);
            }
        }
    }
    __syncthreads();
    unsigned int* gh = g_hist[id];
    for (int i = threadIdx.x; i < 4096; i += 256)
        if (sh[i]) atomicAdd(&gh[i], sh[i]);
}

// exact bin threshold from hist + validate speculative gather
__global__ void check_kernel() {
    int id = blockIdx.x;
    __shared__ unsigned int h[4096];
    __shared__ unsigned int segsum[256];
    int t = threadIdx.x;
    unsigned int mysum = 0;
#pragma unroll
    for (int q = 0; q < 16; q++) {
        unsigned int v = g_hist[id][t * 16 + q];
        h[t * 16 + q] = v;
        mysum += v;
    }
    segsum[t] = mysum;
    __syncthreads();
    for (int d = 1; d < 256; d <<= 1) {
        unsigned int v = segsum[t];
        if (t + d < 256) v += segsum[t + d];
        __syncthreads();
        segsum[t] = v;
        __syncthreads();
    }
    unsigned int cum = (t < 255) ? segsum[t + 1] : 0u;
    for (int q = 15; q >= 0; q--) {
        int bin = t * 16 + q;
        unsigned int hv = h[bin];
        cum += hv;
        if (cum >= PRE && (cum - hv) < PRE) g_thr[id] = ((unsigned int)bin) << 20;
    }
    __syncthreads();
    if (t == 0) {
        unsigned int cnt = g_cnt[id];
        int ok = (cnt >= PRE && cnt <= NCAP);
        g_need[id] = ok ? 0u : 1u;
        if (!ok) g_cnt[id] = 0;
    }
}

// fallback gather (normally immediate exit)
__global__ void __launch_bounds__(256) fallback_kernel(const float4* __restrict__ c0,
                                                       const float4* __restrict__ c1,
                                                       const float4* __restrict__ c2) {
    LvlMap m = map_block(blockIdx.x, c0, c1, c2);
    int id = m.b * 3 + m.lvl;
    if (g_need[id] == 0u) return;
    unsigned int thr = g_thr[id];
    int e = m.start + m.len;
    for (int i = m.start + threadIdx.x; i < e; i += 256) {
        float4 v = m.p[i];
        float c[4] = {v.x, v.y, v.z, v.w};
#pragma unroll
        for (int q = 0; q < 4; q++) {
            float x = c[q];
            if (x >= 1.0f) {
                unsigned int key = __float_as_uint(x) | 0x80000000u;
                if (key >= thr) push_cand(id, i * 4 + q, m.HW, x);
            }
        }
    }
}

// per (img,lvl): sort candidates (size = next pow2 of cnt), decode top-1000
__global__ void topk_decode_kernel(const float* __restrict__ loc0,
                                   const float* __restrict__ loc1,
                                   const float* __restrict__ loc2,
                                   const float* __restrict__ info) {
    extern __shared__ u64 sk[];
    int lvl = blockIdx.x % 3, b = blockIdx.x / 3;
    int id = b * 3 + lvl;
    int tid = threadIdx.x, nt = blockDim.x;
    const int Ht[3] = {80, 40, 20}, St[3] = {8, 16, 32};
    int H = Ht[lvl], W = H, stride = St[lvl];
    const float* loc = (lvl == 0) ? loc0 : ((lvl == 1) ? loc1 : loc2);

    unsigned int cnt = g_cnt[id];
    if (cnt > NCAP) cnt = NCAP;
    int n = 1024;
    while (n < (int)cnt) n <<= 1;
    for (int i = tid; i < n; i += nt)
        sk[i] = (i < (int)cnt) ? g_cand[id][i] : 0ull;
    __syncthreads();
    bitonic_desc(sk, n, tid, nt);

    int HW = H * W;
    float imh = info[b * 5 + 0];
    float imw = info[b * 5 + 1];

    for (int r = tid; r < PRE; r += nt) {
        u64 key = sk[r];
        float* row = g_rois[b][lvl * PRE + r];
        if (key == 0ull) {
            row[0] = row[1] = row[2] = row[3] = row[4] = row[5] = 0.0f;
            continue;
        }
        unsigned int f = 0xFFFFFFFFu - (unsigned int)(key & 0xFFFFFFFFu);
        float score = __uint_as_float((unsigned int)(key >> 32));
        int aidx = f / NC;
        int cc = f - aidx * NC;
        int pp = aidx / NA;
        int a = aidx - pp * NA;
        int hh = pp / W;
        int ww = pp - hh * W;

        int ri = a / 3, si = a % 3;
        double ratio = (ri == 0) ? 0.5 : ((ri == 1) ? 1.0 : 2.0);
        double scale = (si == 0) ? 4.0 : ((si == 1) ? 8.0 : 16.0);
        double basew = (double)stride;
        double ctr = (basew - 1.0) * 0.5;
        double wsd = rint(sqrt(basew * basew / ratio));
        double hsd = rint(wsd * ratio);
        double ax1 = ctr - 0.5 * (wsd - 1.0), ay1 = ctr - 0.5 * (hsd - 1.0);
        double ax2 = ctr + 0.5 * (wsd - 1.0), ay2 = ctr + 0.5 * (hsd - 1.0);
        double aw = ax2 - ax1 + 1.0, ah = ay2 - ay1 + 1.0;
        double cxd = ax1 + 0.5 * (aw - 1.0), cyd = ay1 + 0.5 * (ah - 1.0);
        double swd = aw * scale, shd = ah * scale;
        float bx1 = (float)(cxd - 0.5 * (swd - 1.0));
        float by1 = (float)(cyd - 0.5 * (shd - 1.0));
        float bx2 = (float)(cxd + 0.5 * (swd - 1.0));
        float by2 = (float)(cyd + 0.5 * (shd - 1.0));
        float shx = (float)(ww * stride), shy = (float)(hh * stride);
        float Ax1 = shx + bx1, Ay1 = shy + by1, Ax2 = shx + bx2, Ay2 = shy + by2;

        size_t lbase = ((size_t)b * (NA * 4) + (size_t)a * 4) * (size_t)HW + (size_t)pp;
        float dx = loc[lbase];
        float dy = loc[lbase + HW];
        float dw = loc[lbase + 2 * (size_t)HW];
        float dh = loc[lbase + 3 * (size_t)HW];

        float ws = Ax2 - Ax1 + 1.0f, hs = Ay2 - Ay1 + 1.0f;
        float cx = Ax1 + 0.5f * (ws - 1.0f), cy = Ay1 + 0.5f * (hs - 1.0f);
        dw = fminf(fmaxf(dw, -LOG_MAX_F), LOG_MAX_F);
        dh = fminf(fmaxf(dh, -LOG_MAX_F), LOG_MAX_F);
        float pcx = dx * ws + cx, pcy = dy * hs + cy;
        float pw = expf(dw) * ws, ph = expf(dh) * hs;
        float x1 = pcx - 0.5f * (pw - 1.0f);
        float y1 = pcy - 0.5f * (ph - 1.0f);
        float x2 = pcx + 0.5f * (pw - 1.0f);
        float y2 = pcy + 0.5f * (ph - 1.0f);
        x1 = fminf(fmaxf(x1, 0.0f), imw - 1.0f);
        y1 = fminf(fmaxf(y1, 0.0f), imh - 1.0f);
        x2 = fminf(fmaxf(x2, 0.0f), imw - 1.0f);
        y2 = fminf(fmaxf(y2, 0.0f), imh - 1.0f);

        row[0] = x1; row[1] = y1; row[2] = x2; row[3] = y2;
        row[4] = score;
        row[5] = (float)(cc + 1);
    }
}

// per image: global sort of 3000 by (score desc, pos asc); emit offset boxes SoA
__global__ void nms_sort_kernel() {
    __shared__ u64 keys[4096];
    int b = blockIdx.x, tid = threadIdx.x, nt = blockDim.x;
    for (int i = tid; i < 4096; i += nt) {
        u64 k = 0ull;
        if (i < 3000) {
            float sc = g_rois[b][i][4];
            k = ((u64)__float_as_uint(sc) << 32) | (u64)(0xFFFFFFFFu - (unsigned int)i);
        }
        keys[i] = k;
    }
    __syncthreads();
    bitonic_desc(keys, 4096, tid, nt);
    for (int i = tid; i < 3000; i += nt) {
        int pos = (int)(0xFFFFFFFFu - (unsigned int)(keys[i] & 0xFFFFFFFFu));
        g_spos[b][i] = pos;
        const float* rw = g_rois[b][pos];
        float off = rw[5] * IMG_OFF;
        float a1 = rw[0] + off, b1 = rw[1] + off;
        float a2 = rw[2] + off, b2 = rw[3] + off;
        g_sx1[b][i] = a1; g_sy1[b][i] = b1;
        g_sx2[b][i] = a2; g_sy2[b][i] = b2;
        g_sar[b][i] = (a2 - a1 + 1.0f) * (b2 - b1 + 1.0f);
    }
}

// parallel suppression bitmask: upper-triangle 64x64 tiles
__global__ void __launch_bounds__(64) mask_kernel() {
    int b = blockIdx.y;
    int t = blockIdx.x;
    int ri = 0;
    while (t >= NCH - ri) { t -= NCH - ri; ri++; }
    int ci = ri + t;

    __shared__ float sx1[64], sy1[64], sx2[64], sy2[64], sar[64];
    int col0 = ci * 64;
    int c = col0 + threadIdx.x;
    if (c < 3000) {
        sx1[threadIdx.x] = g_sx1[b][c];
        sy1[threadIdx.x] = g_sy1[b][c];
        sx2[threadIdx.x] = g_sx2[b][c];
        sy2[threadIdx.x] = g_sy2[b][c];
        sar[threadIdx.x] = g_sar[b][c];
    }
    __syncthreads();

    int row = ri * 64 + threadIdx.x;
    if (row >= 3000) return;
    float X1 = g_sx1[b][row], Y1 = g_sy1[b][row];
    float X2 = g_sx2[b][row], Y2 = g_sy2[b][row];
    float AR = g_sar[b][row];

    u64 bits = 0ull;
    int jmax = min(64, 3000 - col0);
#pragma unroll 4
    for (int j = 0; j < jmax; j++) {
        int cidx = col0 + j;
        if (cidx <= row) continue;
        float ltx = fmaxf(X1, sx1[j]);
        float lty = fmaxf(Y1, sy1[j]);
        float rbx = fminf(X2, sx2[j]);
        float rby = fminf(Y2, sy2[j]);
        float w = fmaxf((rbx - ltx) + 1.0f, 0.0f);
        float h = fmaxf((rby - lty) + 1.0f, 0.0f);
        float inter = w * h;
        float iou = inter / ((AR + sar[j]) - inter);
        if (iou > 0.5f) bits |= (1ull << j);
    }
    g_mask[b][row * NCH + ci] = bits;
}

// single-warp greedy scan per image, early exit at 100 kept
__global__ void reduce_kernel(float* __restrict__ out) {
    int b = blockIdx.x, lane = threadIdx.x;
    u64 r0 = 0ull, r1 = 0ull;
    __shared__ int kept[TOPN];
    int k = 0;
    for (int i = 0; i < 3000; i++) {
        int w = i >> 6;
        u64 tmp = (w < 32) ? r0 : r1;
        int owner = (w < 32) ? w : (w - 32);
        u64 val = __shfl_sync(0xFFFFFFFFu, tmp, owner);
        if (!((val >> (i & 63)) & 1ull)) {
            if (lane == 0) kept[k] = i;
            k++;
            if (k == TOPN) break;
            const u64* mrow = &g_mask[b][i * NCH];
            if (lane >= w) r0 |= mrow[lane];
            int W2 = lane + 32;
            if (W2 < NCH && W2 >= w) r1 |= mrow[W2];
        }
    }
    __syncwarp();
    for (int r = lane; r < TOPN; r += 32) {
        float* o = out + ((size_t)b * TOPN + r) * 7;
        if (r < k) {
            int pos = g_spos[b][kept[r]];
            const float* rw = g_rois[b][pos];
            o[0] = (float)b;
            o[1] = rw[0]; o[2] = rw[1]; o[3] = rw[2]; o[4] = rw[3];
            o[5] = rw[4]; o[6] = rw[5];
        } else {
            for (int q = 0; q < 7; q++) o[q] = 0.0f;
        }
    }
}

// ---------------- host launcher ----------------
extern "C" void kernel_launch(void* const* d_in, const int* in_sizes, int n_in,
                              void* d_out, int out_size) {
    (void)in_sizes; (void)n_in; (void)out_size;
    const float4* cls0 = (const float4*)d_in[0];
    const float*  loc0 = (const float*)d_in[1];
    const float4* cls1 = (const float4*)d_in[2];
    const float*  loc1 = (const float*)d_in[3];
    const float4* cls2 = (const float4*)d_in[4];
    const float*  loc2 = (const float*)d_in[5];
    const float*  info = (const float*)d_in[6];
    float* out = (float*)d_out;

    cudaFuncSetAttribute(topk_decode_kernel,
                         cudaFuncAttributeMaxDynamicSharedMemorySize, 65536);

    zero_kernel<<<96, 512>>>();
    passA_kernel<<<1536, 256>>>(cls0, cls1, cls2);
    check_kernel<<<12, 256>>>();
    fallback_kernel<<<1536, 256>>>(cls0, cls1, cls2);
    topk_decode_kernel<<<12, 1024, 65536>>>(loc0, loc1, loc2, info);
    nms_sort_kernel<<<4, 1024>>>();
    mask_kernel<<<dim3(1128, 4), 64>>>();
    reduce_kernel<<<4, 32>>>(out);
}

// round 3
// speedup vs baseline: 3.9752x; 1.6844x over previous
#include <cuda_runtime.h>
#include <math.h>

// ---------------- problem constants ----------------
#define NB    4
#define NLVL  3
#define NA    9
#define NC    80
#define PRE   1000
#define TOPN  100
#define NCAP  8192
#define NCH   47          // ceil(3000/64)
#define LOG_MAX_F 4.135166556742356f
#define IMG_OFF 641.0f

typedef unsigned long long u64;

// ---------------- device scratch ----------------
__device__ unsigned int g_hist[12][4096];
__device__ unsigned int g_cnt [12];
__device__ unsigned int g_thr [12];
__device__ unsigned int g_need[12];
__device__ u64          g_cand[12][NCAP];
__device__ float        g_rois[NB][3000][6];
__device__ u64          g_skey[NB][3000];
__device__ int          g_spos[NB][3008];
__device__ float        g_sx1[NB][3008], g_sy1[NB][3008], g_sx2[NB][3008], g_sy2[NB][3008], g_sar[NB][3008];
__device__ u64          g_mask[NB][3000 * NCH];

// ---------------- helpers ----------------
__device__ __forceinline__ void bitonic_desc(u64* s, int n, int tid, int nt) {
    for (int k = 2; k <= n; k <<= 1) {
        for (int j = k >> 1; j > 0; j >>= 1) {
            for (int i = tid; i < n; i += nt) {
                int ixj = i ^ j;
                if (ixj > i) {
                    u64 a = s[i], b = s[ixj];
                    bool sw = ((i & k) == 0) ? (a < b) : (a > b);
                    if (sw) { s[i] = b; s[ixj] = a; }
                }
            }
            __syncthreads();
        }
    }
}

struct LvlMap {
    int lvl, b, start, len, HW;
    const float4* p;
};
__device__ __forceinline__ LvlMap map_block(int bx, const float4* c0, const float4* c1, const float4* c2) {
    LvlMap m;
    int li, per, nvec;
    if (bx < 1152)      { m.lvl = 0; li = bx;        per = 288; nvec = 1152000; m.HW = 6400; m.p = c0; }
    else if (bx < 1440) { m.lvl = 1; li = bx - 1152; per = 72;  nvec = 288000;  m.HW = 1600; m.p = c1; }
    else                { m.lvl = 2; li = bx - 1440; per = 24;  nvec = 72000;   m.HW = 400;  m.p = c2; }
    m.b = li / per;
    int chunk = li - m.b * per;
    m.len = nvec / per;
    m.start = chunk * m.len;
    m.p += (size_t)m.b * nvec;
    return m;
}

__device__ __forceinline__ void push_cand(int id, int m, int HW, float x) {
    int ch = m / HW;
    int pp = m - ch * HW;
    int a  = ch / NC;
    int cc = ch - a * NC;
    unsigned int f = (unsigned int)((pp * NA + a) * NC + cc);
    float score = 1.0f / (1.0f + expf(-x));
    u64 k64 = ((u64)__float_as_uint(score) << 32) | (u64)(0xFFFFFFFFu - f);
    unsigned int pos = atomicAdd(&g_cnt[id], 1u);
    if (pos < NCAP) g_cand[id][pos] = k64;
}

// ---------------- kernels ----------------
__global__ void zero_kernel() {
    int i = blockIdx.x * blockDim.x + threadIdx.x;
    if (i < 12 * 4096) ((unsigned int*)g_hist)[i] = 0;
    if (i < 12) g_cnt[i] = 0;
}

// one streaming pass: histogram (fallback support) + speculative gather, MLP=4 loads
__global__ void __launch_bounds__(256) passA_kernel(const float4* __restrict__ c0,
                                                    const float4* __restrict__ c1,
                                                    const float4* __restrict__ c2) {
    __shared__ unsigned int sh[4096];
    LvlMap m = map_block(blockIdx.x, c0, c1, c2);
    int id = m.b * 3 + m.lvl;
    float specT = (m.lvl == 0) ? 3.39f : ((m.lvl == 1) ? 2.99f : 2.54f);
    unsigned int specKey = __float_as_uint(specT) | 0x80000000u;

    for (int i = threadIdx.x; i < 4096; i += 256) sh[i] = 0;
    __syncthreads();

    int e = m.start + m.len;
    for (int base = m.start + threadIdx.x; base < e; base += 256 * 4) {
        float4 v[4];
        bool ok[4];
#pragma unroll
        for (int u = 0; u < 4; u++) {
            int idx = base + u * 256;
            ok[u] = idx < e;
            v[u] = ok[u] ? m.p[idx] : make_float4(0.f, 0.f, 0.f, 0.f);
        }
#pragma unroll
        for (int u = 0; u < 4; u++) {
            if (!ok[u]) continue;
            int idx = base + u * 256;
            float c[4] = {v[u].x, v[u].y, v[u].z, v[u].w};
#pragma unroll
            for (int q = 0; q < 4; q++) {
                float x = c[q];
                if (x >= 1.0f) {
                    unsigned int key = __float_as_uint(x) | 0x80000000u;
                    atomicAdd(&sh[key >> 20], 1u);
                    if (key >= specKey) push_cand(id, idx * 4 + q, m.HW, x);
                }
            }
        }
    }
    __syncthreads();
    unsigned int* gh = g_hist[id];
    for (int i = threadIdx.x; i < 4096; i += 256)
        if (sh[i]) atomicAdd(&gh[i], sh[i]);
}

// exact bin threshold from hist + validate speculative gather
__global__ void check_kernel() {
    int id = blockIdx.x;
    __shared__ unsigned int h[4096];
    __shared__ unsigned int segsum[256];
    int t = threadIdx.x;
    unsigned int mysum = 0;
#pragma unroll
    for (int q = 0; q < 16; q++) {
        unsigned int v = g_hist[id][t * 16 + q];
        h[t * 16 + q] = v;
        mysum += v;
    }
    segsum[t] = mysum;
    __syncthreads();
    for (int d = 1; d < 256; d <<= 1) {
        unsigned int v = segsum[t];
        if (t + d < 256) v += segsum[t + d];
        __syncthreads();
        segsum[t] = v;
        __syncthreads();
    }
    unsigned int cum = (t < 255) ? segsum[t + 1] : 0u;
    for (int q = 15; q >= 0; q--) {
        int bin = t * 16 + q;
        unsigned int hv = h[bin];
        cum += hv;
        if (cum >= PRE && (cum - hv) < PRE) g_thr[id] = ((unsigned int)bin) << 20;
    }
    __syncthreads();
    if (t == 0) {
        unsigned int cnt = g_cnt[id];
        int ok = (cnt >= PRE && cnt <= NCAP);
        g_need[id] = ok ? 0u : 1u;
        if (!ok) g_cnt[id] = 0;
    }
}

// fallback gather (normally immediate exit)
__global__ void __launch_bounds__(256) fallback_kernel(const float4* __restrict__ c0,
                                                       const float4* __restrict__ c1,
                                                       const float4* __restrict__ c2) {
    LvlMap m = map_block(blockIdx.x, c0, c1, c2);
    int id = m.b * 3 + m.lvl;
    if (g_need[id] == 0u) return;
    unsigned int thr = g_thr[id];
    int e = m.start + m.len;
    for (int i = m.start + threadIdx.x; i < e; i += 256) {
        float4 v = m.p[i];
        float c[4] = {v.x, v.y, v.z, v.w};
#pragma unroll
        for (int q = 0; q < 4; q++) {
            float x = c[q];
            if (x >= 1.0f) {
                unsigned int key = __float_as_uint(x) | 0x80000000u;
                if (key >= thr) push_cand(id, i * 4 + q, m.HW, x);
            }
        }
    }
}

// per (img,lvl): sort candidates (size = next pow2 of cnt), decode top-1000, emit sorted keys
__global__ void topk_decode_kernel(const float* __restrict__ loc0,
                                   const float* __restrict__ loc1,
                                   const float* __restrict__ loc2,
                                   const float* __restrict__ info) {
    extern __shared__ u64 sk[];
    int lvl = blockIdx.x % 3, b = blockIdx.x / 3;
    int id = b * 3 + lvl;
    int tid = threadIdx.x, nt = blockDim.x;
    const int Ht[3] = {80, 40, 20}, St[3] = {8, 16, 32};
    int H = Ht[lvl], W = H, stride = St[lvl];
    const float* loc = (lvl == 0) ? loc0 : ((lvl == 1) ? loc1 : loc2);

    unsigned int cnt = g_cnt[id];
    if (cnt > NCAP) cnt = NCAP;
    int n = 1024;
    while (n < (int)cnt) n <<= 1;
    for (int i = tid; i < n; i += nt)
        sk[i] = (i < (int)cnt) ? g_cand[id][i] : 0ull;
    __syncthreads();
    bitonic_desc(sk, n, tid, nt);

    int HW = H * W;
    float imh = info[b * 5 + 0];
    float imw = info[b * 5 + 1];

    for (int r = tid; r < PRE; r += nt) {
        u64 key = sk[r];
        int mpos = lvl * PRE + r;
        float* row = g_rois[b][mpos];
        if (key == 0ull) {
            row[0] = row[1] = row[2] = row[3] = row[4] = row[5] = 0.0f;
            g_skey[b][mpos] = (u64)(0xFFFFFFFFu - (unsigned int)mpos);
            continue;
        }
        unsigned int f = 0xFFFFFFFFu - (unsigned int)(key & 0xFFFFFFFFu);
        float score = __uint_as_float((unsigned int)(key >> 32));
        g_skey[b][mpos] = ((u64)__float_as_uint(score) << 32) |
                          (u64)(0xFFFFFFFFu - (unsigned int)mpos);
        int aidx = f / NC;
        int cc = f - aidx * NC;
        int pp = aidx / NA;
        int a = aidx - pp * NA;
        int hh = pp / W;
        int ww = pp - hh * W;

        int ri = a / 3, si = a % 3;
        double ratio = (ri == 0) ? 0.5 : ((ri == 1) ? 1.0 : 2.0);
        double scale = (si == 0) ? 4.0 : ((si == 1) ? 8.0 : 16.0);
        double basew = (double)stride;
        double ctr = (basew - 1.0) * 0.5;
        double wsd = rint(sqrt(basew * basew / ratio));
        double hsd = rint(wsd * ratio);
        double ax1 = ctr - 0.5 * (wsd - 1.0), ay1 = ctr - 0.5 * (hsd - 1.0);
        double ax2 = ctr + 0.5 * (wsd - 1.0), ay2 = ctr + 0.5 * (hsd - 1.0);
        double aw = ax2 - ax1 + 1.0, ah = ay2 - ay1 + 1.0;
        double cxd = ax1 + 0.5 * (aw - 1.0), cyd = ay1 + 0.5 * (ah - 1.0);
        double swd = aw * scale, shd = ah * scale;
        float bx1 = (float)(cxd - 0.5 * (swd - 1.0));
        float by1 = (float)(cyd - 0.5 * (shd - 1.0));
        float bx2 = (float)(cxd + 0.5 * (swd - 1.0));
        float by2 = (float)(cyd + 0.5 * (shd - 1.0));
        float shx = (float)(ww * stride), shy = (float)(hh * stride);
        float Ax1 = shx + bx1, Ay1 = shy + by1, Ax2 = shx + bx2, Ay2 = shy + by2;

        size_t lbase = ((size_t)b * (NA * 4) + (size_t)a * 4) * (size_t)HW + (size_t)pp;
        float dx = loc[lbase];
        float dy = loc[lbase + HW];
        float dw = loc[lbase + 2 * (size_t)HW];
        float dh = loc[lbase + 3 * (size_t)HW];

        float ws = Ax2 - Ax1 + 1.0f, hs = Ay2 - Ay1 + 1.0f;
        float cx = Ax1 + 0.5f * (ws - 1.0f), cy = Ay1 + 0.5f * (hs - 1.0f);
        dw = fminf(fmaxf(dw, -LOG_MAX_F), LOG_MAX_F);
        dh = fminf(fmaxf(dh, -LOG_MAX_F), LOG_MAX_F);
        float pcx = dx * ws + cx, pcy = dy * hs + cy;
        float pw = expf(dw) * ws, ph = expf(dh) * hs;
        float x1 = pcx - 0.5f * (pw - 1.0f);
        float y1 = pcy - 0.5f * (ph - 1.0f);
        float x2 = pcx + 0.5f * (pw - 1.0f);
        float y2 = pcy + 0.5f * (ph - 1.0f);
        x1 = fminf(fmaxf(x1, 0.0f), imw - 1.0f);
        y1 = fminf(fmaxf(y1, 0.0f), imh - 1.0f);
        x2 = fminf(fmaxf(x2, 0.0f), imw - 1.0f);
        y2 = fminf(fmaxf(y2, 0.0f), imh - 1.0f);

        row[0] = x1; row[1] = y1; row[2] = x2; row[3] = y2;
        row[4] = score;
        row[5] = (float)(cc + 1);
    }
}

// per image: 3-way merge of sorted level lists via binary search; emit SoA boxes
__global__ void __launch_bounds__(1024) merge_kernel() {
    __shared__ u64 A[3000];
    int b = blockIdx.x, tid = threadIdx.x;
    for (int i = tid; i < 3000; i += 1024) A[i] = g_skey[b][i];
    __syncthreads();
    for (int i = tid; i < 3000; i += 1024) {
        u64 k = A[i];
        int l = i / 1000;
        int r = i - l * 1000;
        int rank = r;
#pragma unroll
        for (int o = 0; o < 3; o++) {
            if (o == l) continue;
            const u64* arr = &A[o * 1000];
            int lo = 0, hi = 1000;
            while (lo < hi) {
                int mid = (lo + hi) >> 1;
                if (arr[mid] > k) lo = mid + 1; else hi = mid;
            }
            rank += lo;
        }
        g_spos[b][rank] = i;
        const float* rw = g_rois[b][i];
        float off = rw[5] * IMG_OFF;
        float a1 = rw[0] + off, b1 = rw[1] + off;
        float a2 = rw[2] + off, b2 = rw[3] + off;
        g_sx1[b][rank] = a1; g_sy1[b][rank] = b1;
        g_sx2[b][rank] = a2; g_sy2[b][rank] = b2;
        g_sar[b][rank] = (a2 - a1 + 1.0f) * (b2 - b1 + 1.0f);
    }
}

// parallel suppression bitmask: upper-triangle 64x64 tiles
__global__ void __launch_bounds__(64) mask_kernel() {
    int b = blockIdx.y;
    int t = blockIdx.x;
    int ri = 0;
    while (t >= NCH - ri) { t -= NCH - ri; ri++; }
    int ci = ri + t;

    __shared__ float sx1[64], sy1[64], sx2[64], sy2[64], sar[64];
    int col0 = ci * 64;
    int c = col0 + threadIdx.x;
    if (c < 3000) {
        sx1[threadIdx.x] = g_sx1[b][c];
        sy1[threadIdx.x] = g_sy1[b][c];
        sx2[threadIdx.x] = g_sx2[b][c];
        sy2[threadIdx.x] = g_sy2[b][c];
        sar[threadIdx.x] = g_sar[b][c];
    }
    __syncthreads();

    int row = ri * 64 + threadIdx.x;
    if (row >= 3000) return;
    float X1 = g_sx1[b][row], Y1 = g_sy1[b][row];
    float X2 = g_sx2[b][row], Y2 = g_sy2[b][row];
    float AR = g_sar[b][row];

    u64 bits = 0ull;
    int jmax = min(64, 3000 - col0);
#pragma unroll 4
    for (int j = 0; j < jmax; j++) {
        int cidx = col0 + j;
        if (cidx <= row) continue;
        float ltx = fmaxf(X1, sx1[j]);
        float lty = fmaxf(Y1, sy1[j]);
        float rbx = fminf(X2, sx2[j]);
        float rby = fminf(Y2, sy2[j]);
        float w = fmaxf((rbx - ltx) + 1.0f, 0.0f);
        float h = fmaxf((rby - lty) + 1.0f, 0.0f);
        float inter = w * h;
        float iou = inter / ((AR + sar[j]) - inter);
        if (iou > 0.5f) bits |= (1ull << j);
    }
    g_mask[b][row * NCH + ci] = bits;
}

// single-warp greedy scan per image with double-buffered row prefetch
__global__ void __launch_bounds__(32) reduce_kernel(float* __restrict__ out) {
    int b = blockIdx.x, lane = threadIdx.x;
    u64 r0 = 0ull, r1 = 0ull;
    __shared__ int kept[TOPN];
    int k = 0;
    const u64* mb = g_mask[b];
    int lane2 = lane + 32;
    bool has2 = lane2 < NCH;

    u64 cur0[8], cur1[8], nxt0[8], nxt1[8];
#pragma unroll
    for (int d = 0; d < 8; d++) {
        cur0[d] = mb[(size_t)d * NCH + lane];
        cur1[d] = has2 ? mb[(size_t)d * NCH + lane2] : 0ull;
    }

    for (int base = 0; base < 3000 && k < TOPN; base += 8) {
        int nb = base + 8;
#pragma unroll
        for (int d = 0; d < 8; d++) {
            int rr = nb + d;
            bool okr = rr < 3000;
            nxt0[d] = okr ? mb[(size_t)rr * NCH + lane] : 0ull;
            nxt1[d] = (okr && has2) ? mb[(size_t)rr * NCH + lane2] : 0ull;
        }
#pragma unroll
        for (int d = 0; d < 8; d++) {
            int i = base + d;
            int w = i >> 6;
            u64 tmp = (w < 32) ? r0 : r1;
            int owner = (w < 32) ? w : (w - 32);
            u64 val = __shfl_sync(0xFFFFFFFFu, tmp, owner);
            if (!((val >> (i & 63)) & 1ull)) {
                if (lane == 0) kept[k] = i;
                k++;
                if (k == TOPN) break;
                if (lane >= w) r0 |= cur0[d];
                if (has2 && lane2 >= w) r1 |= cur1[d];
            }
        }
#pragma unroll
        for (int d = 0; d < 8; d++) { cur0[d] = nxt0[d]; cur1[d] = nxt1[d]; }
    }
    __syncwarp();

    for (int r = lane; r < TOPN; r += 32) {
        float* o = out + ((size_t)b * TOPN + r) * 7;
        if (r < k) {
            int pos = g_spos[b][kept[r]];
            const float* rw = g_rois[b][pos];
            o[0] = (float)b;
            o[1] = rw[0]; o[2] = rw[1]; o[3] = rw[2]; o[4] = rw[3];
            o[5] = rw[4]; o[6] = rw[5];
        } else {
            for (int q = 0; q < 7; q++) o[q] = 0.0f;
        }
    }
}

// ---------------- host launcher ----------------
extern "C" void kernel_launch(void* const* d_in, const int* in_sizes, int n_in,
                              void* d_out, int out_size) {
    (void)in_sizes; (void)n_in; (void)out_size;
    const float4* cls0 = (const float4*)d_in[0];
    const float*  loc0 = (const float*)d_in[1];
    const float4* cls1 = (const float4*)d_in[2];
    const float*  loc1 = (const float*)d_in[3];
    const float4* cls2 = (const float4*)d_in[4];
    const float*  loc2 = (const float*)d_in[5];
    const float*  info = (const float*)d_in[6];
    float* out = (float*)d_out;

    cudaFuncSetAttribute(topk_decode_kernel,
                         cudaFuncAttributeMaxDynamicSharedMemorySize, 65536);

    zero_kernel<<<96, 512>>>();
    passA_kernel<<<1536, 256>>>(cls0, cls1, cls2);
    check_kernel<<<12, 256>>>();
    fallback_kernel<<<1536, 256>>>(cls0, cls1, cls2);
    topk_decode_kernel<<<12, 1024, 65536>>>(loc0, loc1, loc2, info);
    merge_kernel<<<4, 1024>>>();
    mask_kernel<<<dim3(1128, 4), 64>>>();
    reduce_kernel<<<4, 32>>>(out);
}